// round 14
// baseline (speedup 1.0000x reference)
#include <cuda_runtime.h>
#include <cuda_fp16.h>
#include <math.h>

// ---------------- problem constants ----------------
#define NMAX    50048
#define EMAX    800000
#define IN_DIM  128
#define HEADS   8
#define HID     32
#define D1      256
#define D2      64
#define NEG_SLOPE 0.2f
#define EPS_DEN   1e-16f
#define SLOT    128
#define SLOT_LG 7
#define LOG2E   1.4426950408889634f
#define PA      136     // smem pitch in halves

typedef unsigned long long ull;

// ---------------- device scratch (zero-initialized at module load) ----------------
__device__ __half g_xh[NMAX * IN_DIM];
__device__ __half g_W1h[D1 * IN_DIM];
__device__ __half g_h1h[NMAX * D1];
__device__ __half g_out1h[NMAX * D1];
__device__ float  g_asrc1[NMAX * HEADS]; // pre-scaled by log2(e)
__device__ float  g_adst1[NMAX * HEADS];
__device__ float4 g_node2[NMAX];         // {asrc2*log2e, z0, z1, 0}
__device__ float  g_adst2[NMAX];
__device__ int    g_deg[NMAX];           // zeroed by k_agg2 after final use
__device__ int    g_csr_src[NMAX * SLOT];// stores src*8
__device__ float4 g_ws4[8 * 32];         // W2-folded weights, lane-blocked

// ---------------- helpers ----------------
__device__ __forceinline__ unsigned f2h2(float a, float b) {
    __half2 h = __floats2half2_rn(a, b);
    return *reinterpret_cast<unsigned*>(&h);
}
__device__ __forceinline__ float2 h2f2(unsigned v) {
    __half2 h = *reinterpret_cast<__half2*>(&v);
    return __half22float2(h);
}
__device__ __forceinline__ ull ffma2(ull a, ull b, ull c) {
    ull d;
    asm("fma.rn.f32x2 %0, %1, %2, %3;" : "=l"(d) : "l"(a), "l"(b), "l"(c));
    return d;
}
__device__ __forceinline__ ull pack2(float x) {
    ull d;
    asm("mov.b64 %0, {%1, %1};" : "=l"(d) : "f"(x));
    return d;
}
__device__ __forceinline__ ull f22ull(float2 f) {
    ull d;
    asm("mov.b64 %0, {%1, %2};" : "=l"(d) : "f"(f.x), "f"(f.y));
    return d;
}
__device__ __forceinline__ void unpack2(ull v, float& lo, float& hi) {
    asm("mov.b64 {%0, %1}, %2;" : "=f"(lo), "=f"(hi) : "l"(v));
}
__device__ __forceinline__ float ex2(float x) {
    float y;
    asm("ex2.approx.f32 %0, %1;" : "=f"(y) : "f"(x));
    return y;
}
__device__ __forceinline__ unsigned smem_u32(const void* p) {
    return (unsigned)__cvta_generic_to_shared(p);
}
__device__ __forceinline__ void ldsm_x4(unsigned addr, unsigned& r0, unsigned& r1,
                                        unsigned& r2, unsigned& r3) {
    asm volatile("ldmatrix.sync.aligned.m8n8.x4.shared.b16 {%0,%1,%2,%3}, [%4];"
                 : "=r"(r0), "=r"(r1), "=r"(r2), "=r"(r3) : "r"(addr));
}
__device__ __forceinline__ void mma16816(float* c, const unsigned* a,
                                         unsigned b0, unsigned b1) {
    asm volatile(
        "mma.sync.aligned.m16n8k16.row.col.f32.f16.f16.f32 "
        "{%0,%1,%2,%3}, {%4,%5,%6,%7}, {%8,%9}, {%0,%1,%2,%3};"
        : "+f"(c[0]), "+f"(c[1]), "+f"(c[2]), "+f"(c[3])
        : "r"(a[0]), "r"(a[1]), "r"(a[2]), "r"(a[3]), "r"(b0), "r"(b1));
}
__device__ __forceinline__ float att_w2(float t) {
    return ex2(fmaxf(t, NEG_SLOPE * t));
}
__device__ __forceinline__ __half2 dup_h2(float w) {
    return __floats2half2_rn(w, w);
}

// ---------------- prep kernels ----------------
__global__ void k_scatter(const int* __restrict__ ei, int E, int N) {
    int i = blockIdx.x * blockDim.x + threadIdx.x;
    int ET = E + N;
    if (i >= ET) return;
    int src, dst;
    if (i < E) { src = ei[i]; dst = ei[E + i]; }
    else       { src = i - E; dst = src; }
    int p = atomicAdd(&g_deg[dst], 1);
    if (p < SLOT) g_csr_src[(dst << SLOT_LG) + p] = src * HEADS;
}
__global__ void k_prep_x(const float* __restrict__ x, int n4) {
    int i = blockIdx.x * blockDim.x + threadIdx.x;
    if (i >= n4) return;
    float4 v = ((const float4*)x)[i];
    ((uint2*)g_xh)[i] = make_uint2(f2h2(v.x, v.y), f2h2(v.z, v.w));
}
__global__ void k_prep_w1(const float* __restrict__ W1) {
    int i = blockIdx.x * blockDim.x + threadIdx.x;
    if (i >= D1 * IN_DIM / 4) return;
    float4 v = ((const float4*)W1)[i];
    ((uint2*)g_W1h)[i] = make_uint2(f2h2(v.x, v.y), f2h2(v.z, v.w));
}
// tiny fold: g_ws4 = W2^T @ [as2*L2E, ad2*L2E, fcw0, fcw1], lane-blocked
__global__ void k_fold2(const float* __restrict__ W2,
                        const float* __restrict__ as2, const float* __restrict__ ad2,
                        const float* __restrict__ fcw) {
    int tid = threadIdx.x, lane = tid & 31;
    int s = tid >> 5;                       // 0..7
    int i = s >> 1, ab = s & 1;
    int ch = lane * 8 + i * 2 + ab;         // 0..255
    float d0 = 0.f, d1 = 0.f, d2 = 0.f, d3 = 0.f;
    for (int n = 0; n < D2; n++) {
        float wv = W2[n * D1 + ch];
        d0 += as2[n] * wv;
        d1 += ad2[n] * wv;
        d2 += fcw[n] * wv;
        d3 += fcw[D2 + n] * wv;
    }
    g_ws4[s * 32 + lane] = make_float4(d0 * LOG2E, d1 * LOG2E, d2, d3);
}

// ---------------- GEMM1: 64x64 tiles, smem-staged alpha + coalesced stores -------
__global__ void __launch_bounds__(256) k_gemm1(
        const float* __restrict__ as1, const float* __restrict__ ad1) {
    extern __shared__ __half smh[];
    __half* As = smh;                      // [64][PA]
    __half* Bs = smh + 64 * PA;            // [64][PA]
    float*  sAl = (float*)(smh + 128 * PA);       // [64] as1 slice
    float*  sDl = sAl + 64;                        // [64] ad1 slice
    int tid = threadIdx.x, lane = tid & 31, warp = tid >> 5;
    int row0 = blockIdx.x * 64, col0 = blockIdx.y * 64;

    for (int idx = tid; idx < 64 * 16; idx += 256) {
        int r = idx >> 4, c = idx & 15;
        *(uint4*)&As[r * PA + c * 8] =
            *(const uint4*)&g_xh[(size_t)(row0 + r) * IN_DIM + c * 8];
    }
    for (int idx = tid; idx < 64 * 16; idx += 256) {
        int r = idx >> 4, c = idx & 15;
        *(uint4*)&Bs[r * PA + c * 8] =
            *(const uint4*)&g_W1h[(size_t)(col0 + r) * IN_DIM + c * 8];
    }
    if (tid < 64) {
        sAl[tid] = as1[col0 + tid];
        sDl[tid] = ad1[col0 + tid];
    }
    __syncthreads();

    int wm = warp >> 1, wn = warp & 1;
    int gid = lane >> 2, tig = lane & 3;
    float acc[4][4];
#pragma unroll
    for (int nt = 0; nt < 4; nt++)
#pragma unroll
        for (int j = 0; j < 4; j++) acc[nt][j] = 0.f;

    int ar = lane & 15, ac = (lane >> 4) << 3;
    int bn = ((lane >> 4) << 3) + (lane & 7);
    int bk = ((lane >> 3) & 1) << 3;

#pragma unroll
    for (int ks = 0; ks < 8; ks++) {
        int k0 = ks * 16;
        unsigned a[4];
        unsigned adr = smem_u32(&As[(wm * 16 + ar) * PA + k0 + ac]);
        ldsm_x4(adr, a[0], a[1], a[2], a[3]);
#pragma unroll
        for (int ntp = 0; ntp < 2; ntp++) {
            int n0 = wn * 32 + ntp * 16;
            unsigned b0, b1, b2, b3;
            unsigned bd = smem_u32(&Bs[(n0 + bn) * PA + k0 + bk]);
            ldsm_x4(bd, b0, b1, b2, b3);
            mma16816(acc[ntp * 2],     a, b0, b1);
            mma16816(acc[ntp * 2 + 1], a, b2, b3);
        }
    }

    // alpha partials from smem-staged vectors
    float psA = 0.f, pdA = 0.f, psB = 0.f, pdB = 0.f;
#pragma unroll
    for (int nt = 0; nt < 4; nt++) {
        int cl = wn * 32 + nt * 8 + tig * 2;
        float s0 = sAl[cl], s1 = sAl[cl + 1];
        float d0 = sDl[cl], d1 = sDl[cl + 1];
        psA += acc[nt][0] * s0 + acc[nt][1] * s1;
        pdA += acc[nt][0] * d0 + acc[nt][1] * d1;
        psB += acc[nt][2] * s0 + acc[nt][3] * s1;
        pdB += acc[nt][2] * d0 + acc[nt][3] * d1;
    }
#pragma unroll
    for (int off = 1; off < 4; off <<= 1) {
        psA += __shfl_xor_sync(0xffffffffu, psA, off);
        pdA += __shfl_xor_sync(0xffffffffu, pdA, off);
        psB += __shfl_xor_sync(0xffffffffu, psB, off);
        pdB += __shfl_xor_sync(0xffffffffu, pdB, off);
    }
    int rA = row0 + wm * 16 + gid;
    int rB = rA + 8;
    if (tig == 0) {
        int head = blockIdx.y * 2 + wn;
        g_asrc1[rA * HEADS + head] = psA * LOG2E;
        g_adst1[rA * HEADS + head] = pdA * LOG2E;
        g_asrc1[rB * HEADS + head] = psB * LOG2E;
        g_adst1[rB * HEADS + head] = pdB * LOG2E;
    }

    // staged store: acc -> smem -> coalesced STG.128
    __syncthreads();
    const int CP = 72;
    __half* Cs = smh;
    int rbase = wm * 16 + gid;
#pragma unroll
    for (int nt = 0; nt < 4; nt++) {
        int cl = wn * 32 + nt * 8 + tig * 2;
        *(unsigned*)&Cs[rbase * CP + cl]       = f2h2(acc[nt][0], acc[nt][1]);
        *(unsigned*)&Cs[(rbase + 8) * CP + cl] = f2h2(acc[nt][2], acc[nt][3]);
    }
    __syncthreads();
    for (int idx = tid; idx < 512; idx += 256) {
        int r = idx >> 3, c = idx & 7;
        *(uint4*)&g_h1h[(size_t)(row0 + r) * D1 + col0 + c * 8] =
            *(uint4*)&Cs[r * CP + c * 8];
    }
}

// ---------------- k_node2: GEMV out1h @ ws4 -> {asrc2, adst2, z0, z1} ------------
__global__ void __launch_bounds__(256) k_node2(int N) {
    int gt = blockIdx.x * blockDim.x + threadIdx.x;
    int w = gt >> 5, lane = gt & 31;
    if (w >= N) return;
    float4 wv[8];
#pragma unroll
    for (int s = 0; s < 8; s++) wv[s] = g_ws4[s * 32 + lane];
    uint4 u = *(const uint4*)&g_out1h[(size_t)w * D1 + lane * 8];
    const unsigned* up = &u.x;
    float a0 = 0.f, a1 = 0.f, a2 = 0.f, a3 = 0.f;
#pragma unroll
    for (int i = 0; i < 4; i++) {
        float2 f = h2f2(up[i]);
        float4 wa = wv[i * 2], wb = wv[i * 2 + 1];
        a0 += f.x * wa.x + f.y * wb.x;
        a1 += f.x * wa.y + f.y * wb.y;
        a2 += f.x * wa.z + f.y * wb.z;
        a3 += f.x * wa.w + f.y * wb.w;
    }
#pragma unroll
    for (int off = 16; off; off >>= 1) {
        a0 += __shfl_xor_sync(0xffffffffu, a0, off);
        a1 += __shfl_xor_sync(0xffffffffu, a1, off);
        a2 += __shfl_xor_sync(0xffffffffu, a2, off);
        a3 += __shfl_xor_sync(0xffffffffu, a3, off);
    }
    if (lane == 0) {
        g_node2[w] = make_float4(a0, a2, a3, 0.f);
        g_adst2[w] = a1;
    }
}

// ---------------- layer-1 aggregation (unchanged) ----------------
__device__ __forceinline__ void hacc4(__half2* ha, uint4 u, __half2 w2) {
    ha[0] = __hfma2(*(__half2*)&u.x, w2, ha[0]);
    ha[1] = __hfma2(*(__half2*)&u.y, w2, ha[1]);
    ha[2] = __hfma2(*(__half2*)&u.z, w2, ha[2]);
    ha[3] = __hfma2(*(__half2*)&u.w, w2, ha[3]);
}
__device__ __forceinline__ const uint4* h1row(const __half* Hl, int sH) {
    return (const uint4*)((const char*)Hl + ((size_t)sH << 6));
}

__global__ void __launch_bounds__(256, 6) k_agg1(const float* __restrict__ b1, int N) {
    int gt = blockIdx.x * blockDim.x + threadIdx.x;
    int w = gt >> 5, lane = gt & 31;
    if (w >= N) return;
    int h = lane >> 2;
    float adst = g_adst1[w * HEADS + h];
    ull acc[4];
#pragma unroll
    for (int i = 0; i < 4; i++) acc[i] = 0ull;
    const ull one2 = pack2(1.f);
    float den = 0.f;
    int cnt = g_deg[w]; if (cnt > SLOT) cnt = SLOT;
    const int* row = &g_csr_src[w << SLOT_LG];
    const __half* Hl = g_h1h + lane * 8;

    int e = 0;
    for (; e + 7 < cnt; e += 8) {
        int4 i0 = *(const int4*)&row[e];
        int4 i1 = *(const int4*)&row[e + 4];
        float a0 = g_asrc1[i0.x + h], a1 = g_asrc1[i0.y + h];
        float a2 = g_asrc1[i0.z + h], a3 = g_asrc1[i0.w + h];
        float a4 = g_asrc1[i1.x + h], a5 = g_asrc1[i1.y + h];
        float a6 = g_asrc1[i1.z + h], a7 = g_asrc1[i1.w + h];
        __half2 ha[4];
#pragma unroll
        for (int i = 0; i < 4; i++) ha[i] = __half2half2(__float2half_rn(0.f));
        {
            uint4 u0 = *h1row(Hl, i0.x), u1 = *h1row(Hl, i0.y);
            uint4 u2 = *h1row(Hl, i0.z), u3 = *h1row(Hl, i0.w);
            float w0 = att_w2(a0 + adst), w1 = att_w2(a1 + adst);
            float w2 = att_w2(a2 + adst), w3 = att_w2(a3 + adst);
            den += (w0 + w1) + (w2 + w3);
            hacc4(ha, u0, dup_h2(w0));
            hacc4(ha, u1, dup_h2(w1));
            hacc4(ha, u2, dup_h2(w2));
            hacc4(ha, u3, dup_h2(w3));
        }
        {
            uint4 u0 = *h1row(Hl, i1.x), u1 = *h1row(Hl, i1.y);
            uint4 u2 = *h1row(Hl, i1.z), u3 = *h1row(Hl, i1.w);
            float w0 = att_w2(a4 + adst), w1 = att_w2(a5 + adst);
            float w2 = att_w2(a6 + adst), w3 = att_w2(a7 + adst);
            den += (w0 + w1) + (w2 + w3);
            hacc4(ha, u0, dup_h2(w0));
            hacc4(ha, u1, dup_h2(w1));
            hacc4(ha, u2, dup_h2(w2));
            hacc4(ha, u3, dup_h2(w3));
        }
#pragma unroll
        for (int i = 0; i < 4; i++)
            acc[i] = ffma2(f22ull(__half22float2(ha[i])), one2, acc[i]);
    }
    {
        __half2 ha[4];
#pragma unroll
        for (int i = 0; i < 4; i++) ha[i] = __half2half2(__float2half_rn(0.f));
        for (; e < cnt; e++) {
            int s = row[e];
            float t = g_asrc1[s + h] + adst;
            uint4 u = *h1row(Hl, s);
            float wg = att_w2(t);
            den += wg;
            hacc4(ha, u, dup_h2(wg));
        }
#pragma unroll
        for (int i = 0; i < 4; i++)
            acc[i] = ffma2(f22ull(__half22float2(ha[i])), one2, acc[i]);
    }

    float inv = 1.f / (den + EPS_DEN);
    float4 bb0 = *(const float4*)&b1[lane * 8];
    float4 bb1 = *(const float4*)&b1[lane * 8 + 4];
    float f[8];
    unpack2(acc[0], f[0], f[1]);
    unpack2(acc[1], f[2], f[3]);
    unpack2(acc[2], f[4], f[5]);
    unpack2(acc[3], f[6], f[7]);
    float o[8];
    o[0] = f[0] * inv + bb0.x; o[1] = f[1] * inv + bb0.y;
    o[2] = f[2] * inv + bb0.z; o[3] = f[3] * inv + bb0.w;
    o[4] = f[4] * inv + bb1.x; o[5] = f[5] * inv + bb1.y;
    o[6] = f[6] * inv + bb1.z; o[7] = f[7] * inv + bb1.w;
#pragma unroll
    for (int i = 0; i < 8; i++) o[i] = (o[i] > 0.f) ? o[i] : (__expf(o[i]) - 1.f);
    uint4 pv;
    pv.x = f2h2(o[0], o[1]); pv.y = f2h2(o[2], o[3]);
    pv.z = f2h2(o[4], o[5]); pv.w = f2h2(o[6], o[7]);
    *(uint4*)&g_out1h[(size_t)w * D1 + lane * 8] = pv;
}

// ---------------- layer-2 agg + fc + log-softmax (unchanged) ----------------
__global__ void __launch_bounds__(256, 6) k_agg2(
        const float* __restrict__ b2, const float* __restrict__ fcw,
        const float* __restrict__ fcb, float* __restrict__ out, int N) {
    int gt = blockIdx.x * blockDim.x + threadIdx.x;
    int w = gt >> 5, lane = gt & 31;
    if (w >= N) return;
    float adst = g_adst2[w];
    float den = 0.f, z0 = 0.f, z1 = 0.f;
    int cnt = g_deg[w]; if (cnt > SLOT) cnt = SLOT;
    const int* row = &g_csr_src[w << SLOT_LG];

    for (int e = lane; e < cnt; e += 32) {
        int sH = row[e];
        float4 nd = *(const float4*)((const char*)g_node2 + ((size_t)sH << 1));
        float t = nd.x + adst;
        float wg = ex2(fmaxf(t, NEG_SLOPE * t));
        den += wg;
        z0 += wg * nd.y;
        z1 += wg * nd.z;
    }
    float bl0 = b2[lane * 2], bl1 = b2[lane * 2 + 1];
    float c0 = bl0 * fcw[lane * 2]      + bl1 * fcw[lane * 2 + 1];
    float c1 = bl0 * fcw[64 + lane * 2] + bl1 * fcw[64 + lane * 2 + 1];
#pragma unroll
    for (int off = 16; off; off >>= 1) {
        den += __shfl_xor_sync(0xffffffffu, den, off);
        z0  += __shfl_xor_sync(0xffffffffu, z0,  off);
        z1  += __shfl_xor_sync(0xffffffffu, z1,  off);
        c0  += __shfl_xor_sync(0xffffffffu, c0,  off);
        c1  += __shfl_xor_sync(0xffffffffu, c1,  off);
    }
    if (lane == 0) {
        g_deg[w] = 0;
        float inv = 1.f / (den + EPS_DEN);
        float l0 = z0 * inv + c0 + fcb[0];
        float l1 = z1 * inv + c1 + fcb[1];
        float m = fmaxf(l0, l1);
        float lse = m + logf(expf(l0 - m) + expf(l1 - m));
        out[(size_t)w * 2 + 0] = l0 - lse;
        out[(size_t)w * 2 + 1] = l1 - lse;
    }
}

// ---------------- launch ----------------
extern "C" void kernel_launch(void* const* d_in, const int* in_sizes, int n_in,
                              void* d_out, int out_size) {
    const float* x   = (const float*)d_in[0];
    const int*   ei  = (const int*)  d_in[1];
    const float* W1  = (const float*)d_in[2];
    const float* as1 = (const float*)d_in[3];
    const float* ad1 = (const float*)d_in[4];
    const float* b1  = (const float*)d_in[5];
    const float* W2  = (const float*)d_in[6];
    const float* as2 = (const float*)d_in[7];
    const float* ad2 = (const float*)d_in[8];
    const float* b2  = (const float*)d_in[9];
    const float* fcw = (const float*)d_in[10];
    const float* fcb = (const float*)d_in[11];
    float* out = (float*)d_out;

    int N  = in_sizes[0] / IN_DIM;
    int E  = in_sizes[1] / 2;
    int ET = E + N;
    int NB64 = (N + 63) / 64;

    const int SMEM1 = (64 + 64) * PA * 2 + 512;   // 35,328 B
    cudaFuncSetAttribute(k_gemm1, cudaFuncAttributeMaxDynamicSharedMemorySize, SMEM1);

    // 1: padded-slot CSR scatter
    k_scatter<<<(ET + 255) / 256, 256>>>(ei, E, N);
    // 2-4: fp16 conversions + W2 fold
    k_prep_x<<<(N * IN_DIM / 4 + 255) / 256, 256>>>(x, N * IN_DIM / 4);
    k_prep_w1<<<(D1 * IN_DIM / 4 + 255) / 256, 256>>>(W1);
    k_fold2<<<1, 256>>>(W2, as2, ad2, fcw);
    // 5: layer-1 projection + alpha1 (smem-staged epilogue)
    k_gemm1<<<dim3(NB64, 4), 256, SMEM1>>>(as1, ad1);
    // 6: layer-1 aggregation
    k_agg1<<<(N + 7) / 8, 256>>>(b1, N);
    // 7: node2 GEMV (replaces gemm2)
    k_node2<<<(N + 7) / 8, 256>>>(N);
    // 8: layer-2 aggregation + fc + log_softmax (+ g_deg reset)
    k_agg2<<<(N + 7) / 8, 256>>>(b2, fcw, fcb, out, N);
}

// round 15
// speedup vs baseline: 1.3989x; 1.3989x over previous
#include <cuda_runtime.h>
#include <cuda_fp16.h>
#include <math.h>

// ---------------- problem constants ----------------
#define NMAX    50048
#define EMAX    800000
#define IN_DIM  128
#define HEADS   8
#define HID     32
#define D1      256
#define D2      64
#define NEG_SLOPE 0.2f
#define EPS_DEN   1e-16f
#define SLOT    128
#define SLOT_LG 7
#define LOG2E   1.4426950408889634f
#define PA      136     // smem pitch in halves

typedef unsigned long long ull;

// ---------------- device scratch (zero-initialized at module load) ----------------
__device__ __half g_xh[NMAX * IN_DIM];
__device__ __half g_W1h[D1 * IN_DIM];
__device__ __half g_h1h[NMAX * D1];
__device__ __half g_out1h[NMAX * D1];
__device__ float  g_asrc1[NMAX * HEADS]; // pre-scaled by log2(e)
__device__ float  g_adst1[NMAX * HEADS];
__device__ float4 g_node2[NMAX];         // {asrc2*log2e, z0, z1, 0}
__device__ float  g_adst2[NMAX];
__device__ int    g_deg[NMAX];           // zeroed by k_agg2 after final use
__device__ int    g_csr_src[NMAX * SLOT];// stores src*8
__device__ float4 g_ws4[8 * 32];         // W2-folded weights, lane-blocked

// ---------------- helpers ----------------
__device__ __forceinline__ unsigned f2h2(float a, float b) {
    __half2 h = __floats2half2_rn(a, b);
    return *reinterpret_cast<unsigned*>(&h);
}
__device__ __forceinline__ float2 h2f2(unsigned v) {
    __half2 h = *reinterpret_cast<__half2*>(&v);
    return __half22float2(h);
}
__device__ __forceinline__ ull ffma2(ull a, ull b, ull c) {
    ull d;
    asm("fma.rn.f32x2 %0, %1, %2, %3;" : "=l"(d) : "l"(a), "l"(b), "l"(c));
    return d;
}
__device__ __forceinline__ ull pack2(float x) {
    ull d;
    asm("mov.b64 %0, {%1, %1};" : "=l"(d) : "f"(x));
    return d;
}
__device__ __forceinline__ ull f22ull(float2 f) {
    ull d;
    asm("mov.b64 %0, {%1, %2};" : "=l"(d) : "f"(f.x), "f"(f.y));
    return d;
}
__device__ __forceinline__ void unpack2(ull v, float& lo, float& hi) {
    asm("mov.b64 {%0, %1}, %2;" : "=f"(lo), "=f"(hi) : "l"(v));
}
__device__ __forceinline__ float ex2(float x) {
    float y;
    asm("ex2.approx.f32 %0, %1;" : "=f"(y) : "f"(x));
    return y;
}
__device__ __forceinline__ unsigned smem_u32(const void* p) {
    return (unsigned)__cvta_generic_to_shared(p);
}
__device__ __forceinline__ void ldsm_x4(unsigned addr, unsigned& r0, unsigned& r1,
                                        unsigned& r2, unsigned& r3) {
    asm volatile("ldmatrix.sync.aligned.m8n8.x4.shared.b16 {%0,%1,%2,%3}, [%4];"
                 : "=r"(r0), "=r"(r1), "=r"(r2), "=r"(r3) : "r"(addr));
}
__device__ __forceinline__ void mma16816(float* c, const unsigned* a,
                                         unsigned b0, unsigned b1) {
    asm volatile(
        "mma.sync.aligned.m16n8k16.row.col.f32.f16.f16.f32 "
        "{%0,%1,%2,%3}, {%4,%5,%6,%7}, {%8,%9}, {%0,%1,%2,%3};"
        : "+f"(c[0]), "+f"(c[1]), "+f"(c[2]), "+f"(c[3])
        : "r"(a[0]), "r"(a[1]), "r"(a[2]), "r"(a[3]), "r"(b0), "r"(b1));
}
__device__ __forceinline__ float att_w2(float t) {
    return ex2(fmaxf(t, NEG_SLOPE * t));
}
__device__ __forceinline__ __half2 dup_h2(float w) {
    return __floats2half2_rn(w, w);
}

// ---------------- merged prep + scatter (R11 structure, W2 conversion dropped) ---
// block ranges: [0, SB) scatter | [SB, SB+XB) x fp16 | [SB+XB, ..) W1 fp16
__global__ void k_prep(const float* __restrict__ x,
                       const float* __restrict__ W1,
                       const int* __restrict__ ei, int E, int N,
                       int SB, int XB) {
    int b = blockIdx.x;
    int tid = threadIdx.x;
    if (b < SB) {
        int i = b * 256 + tid;
        int ET = E + N;
        if (i >= ET) return;
        int src, dst;
        if (i < E) { src = ei[i]; dst = ei[E + i]; }
        else       { src = i - E; dst = src; }
        int p = atomicAdd(&g_deg[dst], 1);
        if (p < SLOT) g_csr_src[(dst << SLOT_LG) + p] = src * HEADS;
    } else if (b < SB + XB) {
        int i = (b - SB) * 256 + tid;
        int n4 = N * IN_DIM / 4;
        if (i >= n4) return;
        float4 v = ((const float4*)x)[i];
        ((uint2*)g_xh)[i] = make_uint2(f2h2(v.x, v.y), f2h2(v.z, v.w));
    } else {
        int i = (b - SB - XB) * 256 + tid;
        if (i >= D1 * IN_DIM / 4) return;
        float4 v = ((const float4*)W1)[i];
        ((uint2*)g_W1h)[i] = make_uint2(f2h2(v.x, v.y), f2h2(v.z, v.w));
    }
}

// ---------------- k_fold2c: coalesced W2 fold (replaces gemm2's weight side) -----
// g_ws4[s*32+lane] = folded vec for channel ch = lane*8 + s.
// thread t owns channel t; loop over n with fully coalesced W2 row loads.
__global__ void k_fold2c(const float* __restrict__ W2,
                         const float* __restrict__ as2, const float* __restrict__ ad2,
                         const float* __restrict__ fcw) {
    int t = threadIdx.x;   // 0..255 = channel
    float d0 = 0.f, d1 = 0.f, d2 = 0.f, d3 = 0.f;
    for (int n = 0; n < D2; n++) {
        float wv = W2[n * D1 + t];      // coalesced across threads
        float s = as2[n], d = ad2[n];   // broadcast
        float f0 = fcw[n], f1 = fcw[D2 + n];
        d0 += s * wv;
        d1 += d * wv;
        d2 += f0 * wv;
        d3 += f1 * wv;
    }
    g_ws4[(t & 7) * 32 + (t >> 3)] = make_float4(d0 * LOG2E, d1 * LOG2E, d2, d3);
}

// ---------------- GEMM1: 64x64 tiles (R11 verbatim), fused alpha1 ----------------
__global__ void __launch_bounds__(256) k_gemm1(
        const float* __restrict__ as1, const float* __restrict__ ad1) {
    extern __shared__ __half smh[];
    __half* As = smh;              // [64][PA]
    __half* Bs = smh + 64 * PA;    // [64][PA]
    int tid = threadIdx.x, lane = tid & 31, warp = tid >> 5;
    int row0 = blockIdx.x * 64, col0 = blockIdx.y * 64;

    for (int idx = tid; idx < 64 * 16; idx += 256) {
        int r = idx >> 4, c = idx & 15;
        *(uint4*)&As[r * PA + c * 8] =
            *(const uint4*)&g_xh[(size_t)(row0 + r) * IN_DIM + c * 8];
    }
    for (int idx = tid; idx < 64 * 16; idx += 256) {
        int r = idx >> 4, c = idx & 15;
        *(uint4*)&Bs[r * PA + c * 8] =
            *(const uint4*)&g_W1h[(size_t)(col0 + r) * IN_DIM + c * 8];
    }
    __syncthreads();

    int wm = warp >> 1, wn = warp & 1;
    int gid = lane >> 2, tig = lane & 3;
    float acc[4][4];
#pragma unroll
    for (int nt = 0; nt < 4; nt++)
#pragma unroll
        for (int j = 0; j < 4; j++) acc[nt][j] = 0.f;

    int ar = lane & 15, ac = (lane >> 4) << 3;
    int bn = ((lane >> 4) << 3) + (lane & 7);
    int bk = ((lane >> 3) & 1) << 3;

#pragma unroll
    for (int ks = 0; ks < 8; ks++) {
        int k0 = ks * 16;
        unsigned a[4];
        unsigned adr = smem_u32(&As[(wm * 16 + ar) * PA + k0 + ac]);
        ldsm_x4(adr, a[0], a[1], a[2], a[3]);
#pragma unroll
        for (int ntp = 0; ntp < 2; ntp++) {
            int n0 = wn * 32 + ntp * 16;
            unsigned b0, b1, b2, b3;
            unsigned bd = smem_u32(&Bs[(n0 + bn) * PA + k0 + bk]);
            ldsm_x4(bd, b0, b1, b2, b3);
            mma16816(acc[ntp * 2],     a, b0, b1);
            mma16816(acc[ntp * 2 + 1], a, b2, b3);
        }
    }

    int rA = row0 + wm * 16 + gid;
    int rB = rA + 8;
#pragma unroll
    for (int nt = 0; nt < 4; nt++) {
        int col = col0 + wn * 32 + nt * 8 + tig * 2;
        *(unsigned*)&g_h1h[(size_t)rA * D1 + col] = f2h2(acc[nt][0], acc[nt][1]);
        *(unsigned*)&g_h1h[(size_t)rB * D1 + col] = f2h2(acc[nt][2], acc[nt][3]);
    }
    float psA = 0.f, pdA = 0.f, psB = 0.f, pdB = 0.f;
#pragma unroll
    for (int nt = 0; nt < 4; nt++) {
        int col = col0 + wn * 32 + nt * 8 + tig * 2;
        float s0 = as1[col], s1 = as1[col + 1];
        float d0 = ad1[col], d1 = ad1[col + 1];
        psA += acc[nt][0] * s0 + acc[nt][1] * s1;
        pdA += acc[nt][0] * d0 + acc[nt][1] * d1;
        psB += acc[nt][2] * s0 + acc[nt][3] * s1;
        pdB += acc[nt][2] * d0 + acc[nt][3] * d1;
    }
#pragma unroll
    for (int off = 1; off < 4; off <<= 1) {
        psA += __shfl_xor_sync(0xffffffffu, psA, off);
        pdA += __shfl_xor_sync(0xffffffffu, pdA, off);
        psB += __shfl_xor_sync(0xffffffffu, psB, off);
        pdB += __shfl_xor_sync(0xffffffffu, pdB, off);
    }
    if (tig == 0) {
        int head = blockIdx.y * 2 + wn;
        g_asrc1[rA * HEADS + head] = psA * LOG2E;
        g_adst1[rA * HEADS + head] = pdA * LOG2E;
        g_asrc1[rB * HEADS + head] = psB * LOG2E;
        g_adst1[rB * HEADS + head] = pdB * LOG2E;
    }
}

// ---------------- k_node2: GEMV out1h @ ws4 -> {asrc2, adst2, z0, z1} ------------
__global__ void __launch_bounds__(256) k_node2(int N) {
    int gt = blockIdx.x * blockDim.x + threadIdx.x;
    int w = gt >> 5, lane = gt & 31;
    if (w >= N) return;
    float4 wv[8];
#pragma unroll
    for (int s = 0; s < 8; s++) wv[s] = g_ws4[s * 32 + lane];
    uint4 u = *(const uint4*)&g_out1h[(size_t)w * D1 + lane * 8];
    const unsigned* up = &u.x;
    float a0 = 0.f, a1 = 0.f, a2 = 0.f, a3 = 0.f;
#pragma unroll
    for (int i = 0; i < 4; i++) {
        float2 f = h2f2(up[i]);
        float4 wa = wv[i * 2], wb = wv[i * 2 + 1];
        a0 += f.x * wa.x + f.y * wb.x;
        a1 += f.x * wa.y + f.y * wb.y;
        a2 += f.x * wa.z + f.y * wb.z;
        a3 += f.x * wa.w + f.y * wb.w;
    }
#pragma unroll
    for (int off = 16; off; off >>= 1) {
        a0 += __shfl_xor_sync(0xffffffffu, a0, off);
        a1 += __shfl_xor_sync(0xffffffffu, a1, off);
        a2 += __shfl_xor_sync(0xffffffffu, a2, off);
        a3 += __shfl_xor_sync(0xffffffffu, a3, off);
    }
    if (lane == 0) {
        g_node2[w] = make_float4(a0, a2, a3, 0.f);
        g_adst2[w] = a1;
    }
}

// ---------------- layer-1 aggregation (R11 verbatim) ----------------
__device__ __forceinline__ void hacc4(__half2* ha, uint4 u, __half2 w2) {
    ha[0] = __hfma2(*(__half2*)&u.x, w2, ha[0]);
    ha[1] = __hfma2(*(__half2*)&u.y, w2, ha[1]);
    ha[2] = __hfma2(*(__half2*)&u.z, w2, ha[2]);
    ha[3] = __hfma2(*(__half2*)&u.w, w2, ha[3]);
}
__device__ __forceinline__ const uint4* h1row(const __half* Hl, int sH) {
    return (const uint4*)((const char*)Hl + ((size_t)sH << 6));
}

__global__ void __launch_bounds__(256, 6) k_agg1(const float* __restrict__ b1, int N) {
    int gt = blockIdx.x * blockDim.x + threadIdx.x;
    int w = gt >> 5, lane = gt & 31;
    if (w >= N) return;
    int h = lane >> 2;
    float adst = g_adst1[w * HEADS + h];
    ull acc[4];
#pragma unroll
    for (int i = 0; i < 4; i++) acc[i] = 0ull;
    const ull one2 = pack2(1.f);
    float den = 0.f;
    int cnt = g_deg[w]; if (cnt > SLOT) cnt = SLOT;
    const int* row = &g_csr_src[w << SLOT_LG];
    const __half* Hl = g_h1h + lane * 8;

    int e = 0;
    for (; e + 7 < cnt; e += 8) {
        int4 i0 = *(const int4*)&row[e];
        int4 i1 = *(const int4*)&row[e + 4];
        float a0 = g_asrc1[i0.x + h], a1 = g_asrc1[i0.y + h];
        float a2 = g_asrc1[i0.z + h], a3 = g_asrc1[i0.w + h];
        float a4 = g_asrc1[i1.x + h], a5 = g_asrc1[i1.y + h];
        float a6 = g_asrc1[i1.z + h], a7 = g_asrc1[i1.w + h];
        __half2 ha[4];
#pragma unroll
        for (int i = 0; i < 4; i++) ha[i] = __half2half2(__float2half_rn(0.f));
        {
            uint4 u0 = *h1row(Hl, i0.x), u1 = *h1row(Hl, i0.y);
            uint4 u2 = *h1row(Hl, i0.z), u3 = *h1row(Hl, i0.w);
            float w0 = att_w2(a0 + adst), w1 = att_w2(a1 + adst);
            float w2 = att_w2(a2 + adst), w3 = att_w2(a3 + adst);
            den += (w0 + w1) + (w2 + w3);
            hacc4(ha, u0, dup_h2(w0));
            hacc4(ha, u1, dup_h2(w1));
            hacc4(ha, u2, dup_h2(w2));
            hacc4(ha, u3, dup_h2(w3));
        }
        {
            uint4 u0 = *h1row(Hl, i1.x), u1 = *h1row(Hl, i1.y);
            uint4 u2 = *h1row(Hl, i1.z), u3 = *h1row(Hl, i1.w);
            float w0 = att_w2(a4 + adst), w1 = att_w2(a5 + adst);
            float w2 = att_w2(a6 + adst), w3 = att_w2(a7 + adst);
            den += (w0 + w1) + (w2 + w3);
            hacc4(ha, u0, dup_h2(w0));
            hacc4(ha, u1, dup_h2(w1));
            hacc4(ha, u2, dup_h2(w2));
            hacc4(ha, u3, dup_h2(w3));
        }
#pragma unroll
        for (int i = 0; i < 4; i++)
            acc[i] = ffma2(f22ull(__half22float2(ha[i])), one2, acc[i]);
    }
    {
        __half2 ha[4];
#pragma unroll
        for (int i = 0; i < 4; i++) ha[i] = __half2half2(__float2half_rn(0.f));
        for (; e < cnt; e++) {
            int s = row[e];
            float t = g_asrc1[s + h] + adst;
            uint4 u = *h1row(Hl, s);
            float wg = att_w2(t);
            den += wg;
            hacc4(ha, u, dup_h2(wg));
        }
#pragma unroll
        for (int i = 0; i < 4; i++)
            acc[i] = ffma2(f22ull(__half22float2(ha[i])), one2, acc[i]);
    }

    float inv = 1.f / (den + EPS_DEN);
    float4 bb0 = *(const float4*)&b1[lane * 8];
    float4 bb1 = *(const float4*)&b1[lane * 8 + 4];
    float f[8];
    unpack2(acc[0], f[0], f[1]);
    unpack2(acc[1], f[2], f[3]);
    unpack2(acc[2], f[4], f[5]);
    unpack2(acc[3], f[6], f[7]);
    float o[8];
    o[0] = f[0] * inv + bb0.x; o[1] = f[1] * inv + bb0.y;
    o[2] = f[2] * inv + bb0.z; o[3] = f[3] * inv + bb0.w;
    o[4] = f[4] * inv + bb1.x; o[5] = f[5] * inv + bb1.y;
    o[6] = f[6] * inv + bb1.z; o[7] = f[7] * inv + bb1.w;
#pragma unroll
    for (int i = 0; i < 8; i++) o[i] = (o[i] > 0.f) ? o[i] : (__expf(o[i]) - 1.f);
    uint4 pv;
    pv.x = f2h2(o[0], o[1]); pv.y = f2h2(o[2], o[3]);
    pv.z = f2h2(o[4], o[5]); pv.w = f2h2(o[6], o[7]);
    *(uint4*)&g_out1h[(size_t)w * D1 + lane * 8] = pv;
}

// ---------------- layer-2 agg + fc + log-softmax (R11 verbatim) ----------------
__global__ void __launch_bounds__(256, 6) k_agg2(
        const float* __restrict__ b2, const float* __restrict__ fcw,
        const float* __restrict__ fcb, float* __restrict__ out, int N) {
    int gt = blockIdx.x * blockDim.x + threadIdx.x;
    int w = gt >> 5, lane = gt & 31;
    if (w >= N) return;
    float adst = g_adst2[w];
    float den = 0.f, z0 = 0.f, z1 = 0.f;
    int cnt = g_deg[w]; if (cnt > SLOT) cnt = SLOT;
    const int* row = &g_csr_src[w << SLOT_LG];

    for (int e = lane; e < cnt; e += 32) {
        int sH = row[e];
        float4 nd = *(const float4*)((const char*)g_node2 + ((size_t)sH << 1));
        float t = nd.x + adst;
        float wg = ex2(fmaxf(t, NEG_SLOPE * t));
        den += wg;
        z0 += wg * nd.y;
        z1 += wg * nd.z;
    }
    float bl0 = b2[lane * 2], bl1 = b2[lane * 2 + 1];
    float c0 = bl0 * fcw[lane * 2]      + bl1 * fcw[lane * 2 + 1];
    float c1 = bl0 * fcw[64 + lane * 2] + bl1 * fcw[64 + lane * 2 + 1];
#pragma unroll
    for (int off = 16; off; off >>= 1) {
        den += __shfl_xor_sync(0xffffffffu, den, off);
        z0  += __shfl_xor_sync(0xffffffffu, z0,  off);
        z1  += __shfl_xor_sync(0xffffffffu, z1,  off);
        c0  += __shfl_xor_sync(0xffffffffu, c0,  off);
        c1  += __shfl_xor_sync(0xffffffffu, c1,  off);
    }
    if (lane == 0) {
        g_deg[w] = 0;
        float inv = 1.f / (den + EPS_DEN);
        float l0 = z0 * inv + c0 + fcb[0];
        float l1 = z1 * inv + c1 + fcb[1];
        float m = fmaxf(l0, l1);
        float lse = m + logf(expf(l0 - m) + expf(l1 - m));
        out[(size_t)w * 2 + 0] = l0 - lse;
        out[(size_t)w * 2 + 1] = l1 - lse;
    }
}

// ---------------- launch ----------------
extern "C" void kernel_launch(void* const* d_in, const int* in_sizes, int n_in,
                              void* d_out, int out_size) {
    const float* x   = (const float*)d_in[0];
    const int*   ei  = (const int*)  d_in[1];
    const float* W1  = (const float*)d_in[2];
    const float* as1 = (const float*)d_in[3];
    const float* ad1 = (const float*)d_in[4];
    const float* b1  = (const float*)d_in[5];
    const float* W2  = (const float*)d_in[6];
    const float* as2 = (const float*)d_in[7];
    const float* ad2 = (const float*)d_in[8];
    const float* b2  = (const float*)d_in[9];
    const float* fcw = (const float*)d_in[10];
    const float* fcb = (const float*)d_in[11];
    float* out = (float*)d_out;

    int N  = in_sizes[0] / IN_DIM;
    int E  = in_sizes[1] / 2;
    int ET = E + N;
    int NB64 = (N + 63) / 64;

    const int SMEM = (64 + 64) * PA * 2;   // 34,816 B
    cudaFuncSetAttribute(k_gemm1, cudaFuncAttributeMaxDynamicSharedMemorySize, SMEM);

    // 1: merged scatter + fp16 conversions (R11 structure)
    int SB = (ET + 255) / 256;
    int XB = (N * IN_DIM / 4 + 255) / 256;
    int WB = (D1 * IN_DIM / 4 + 255) / 256;
    k_prep<<<SB + XB + WB, 256>>>(x, W1, ei, E, N, SB, XB);
    // 2: coalesced W2 fold (tiny)
    k_fold2c<<<1, 256>>>(W2, as2, ad2, fcw);
    // 3: layer-1 projection + alpha1
    k_gemm1<<<dim3(NB64, 4), 256, SMEM>>>(as1, ad1);
    // 4: layer-1 aggregation  (profiled slot)
    k_agg1<<<(N + 7) / 8, 256>>>(b1, N);
    // 5: node2 GEMV (replaces gemm2)
    k_node2<<<(N + 7) / 8, 256>>>(N);
    // 6: layer-2 aggregation + fc + log_softmax (+ g_deg reset)
    k_agg2<<<(N + 7) / 8, 256>>>(b2, fcw, fcb, out, N);
}

// round 16
// speedup vs baseline: 1.5669x; 1.1201x over previous
#include <cuda_runtime.h>
#include <cuda_fp16.h>
#include <math.h>

// ---------------- problem constants ----------------
#define NMAX    50048
#define EMAX    800000
#define IN_DIM  128
#define HEADS   8
#define HID     32
#define D1      256
#define D2      64
#define NEG_SLOPE 0.2f
#define EPS_DEN   1e-16f
#define SLOT    128
#define SLOT_LG 7
#define LOG2E   1.4426950408889634f
#define PA      136     // smem pitch in halves

typedef unsigned long long ull;

// ---------------- device scratch (zero-initialized at module load) ----------------
__device__ __half g_xh[NMAX * IN_DIM];
__device__ __half g_W1h[D1 * IN_DIM];
__device__ __half g_h1h[NMAX * D1];
__device__ __half g_out1h[NMAX * D1];
__device__ float  g_asrc1[NMAX * HEADS]; // pre-scaled by log2(e)
__device__ float  g_adst1[NMAX * HEADS];
__device__ float4 g_node2[NMAX];         // {asrc2*log2e, z0, z1, 0}
__device__ float  g_adst2[NMAX];
__device__ int    g_deg[NMAX];           // zeroed by k_agg2 after final use
__device__ int    g_csr_src[NMAX * SLOT];// stores src*8
__device__ float4 g_ws4[8 * 32];         // W2-folded weights, lane-blocked

// ---------------- helpers ----------------
__device__ __forceinline__ unsigned f2h2(float a, float b) {
    __half2 h = __floats2half2_rn(a, b);
    return *reinterpret_cast<unsigned*>(&h);
}
__device__ __forceinline__ float2 h2f2(unsigned v) {
    __half2 h = *reinterpret_cast<__half2*>(&v);
    return __half22float2(h);
}
__device__ __forceinline__ ull ffma2(ull a, ull b, ull c) {
    ull d;
    asm("fma.rn.f32x2 %0, %1, %2, %3;" : "=l"(d) : "l"(a), "l"(b), "l"(c));
    return d;
}
__device__ __forceinline__ ull pack2(float x) {
    ull d;
    asm("mov.b64 %0, {%1, %1};" : "=l"(d) : "f"(x));
    return d;
}
__device__ __forceinline__ ull f22ull(float2 f) {
    ull d;
    asm("mov.b64 %0, {%1, %2};" : "=l"(d) : "f"(f.x), "f"(f.y));
    return d;
}
__device__ __forceinline__ void unpack2(ull v, float& lo, float& hi) {
    asm("mov.b64 {%0, %1}, %2;" : "=f"(lo), "=f"(hi) : "l"(v));
}
__device__ __forceinline__ float ex2(float x) {
    float y;
    asm("ex2.approx.f32 %0, %1;" : "=f"(y) : "f"(x));
    return y;
}
__device__ __forceinline__ unsigned smem_u32(const void* p) {
    return (unsigned)__cvta_generic_to_shared(p);
}
__device__ __forceinline__ void ldsm_x4(unsigned addr, unsigned& r0, unsigned& r1,
                                        unsigned& r2, unsigned& r3) {
    asm volatile("ldmatrix.sync.aligned.m8n8.x4.shared.b16 {%0,%1,%2,%3}, [%4];"
                 : "=r"(r0), "=r"(r1), "=r"(r2), "=r"(r3) : "r"(addr));
}
__device__ __forceinline__ void mma16816(float* c, const unsigned* a,
                                         unsigned b0, unsigned b1) {
    asm volatile(
        "mma.sync.aligned.m16n8k16.row.col.f32.f16.f16.f32 "
        "{%0,%1,%2,%3}, {%4,%5,%6,%7}, {%8,%9}, {%0,%1,%2,%3};"
        : "+f"(c[0]), "+f"(c[1]), "+f"(c[2]), "+f"(c[3])
        : "r"(a[0]), "r"(a[1]), "r"(a[2]), "r"(a[3]), "r"(b0), "r"(b1));
}
__device__ __forceinline__ float att_w2(float t) {
    return ex2(fmaxf(t, NEG_SLOPE * t));
}
__device__ __forceinline__ __half2 dup_h2(float w) {
    return __floats2half2_rn(w, w);
}

// ---------------- merged prep: scatter | x fp16 | W1 fp16 | W2 fold (1 block) ----
__global__ void k_prep(const float* __restrict__ x,
                       const float* __restrict__ W1, const float* __restrict__ W2,
                       const float* __restrict__ as2, const float* __restrict__ ad2,
                       const float* __restrict__ fcw,
                       const int* __restrict__ ei, int E, int N,
                       int SB, int XB, int WB) {
    int b = blockIdx.x;
    int tid = threadIdx.x;
    if (b < SB) {                        // scatter
        int i = b * 256 + tid;
        int ET = E + N;
        if (i >= ET) return;
        int src, dst;
        if (i < E) { src = ei[i]; dst = ei[E + i]; }
        else       { src = i - E; dst = src; }
        int p = atomicAdd(&g_deg[dst], 1);
        if (p < SLOT) g_csr_src[(dst << SLOT_LG) + p] = src * HEADS;
    } else if (b < SB + XB) {            // x -> fp16
        int i = (b - SB) * 256 + tid;
        int n4 = N * IN_DIM / 4;
        if (i >= n4) return;
        float4 v = ((const float4*)x)[i];
        ((uint2*)g_xh)[i] = make_uint2(f2h2(v.x, v.y), f2h2(v.z, v.w));
    } else if (b < SB + XB + WB) {       // W1 -> fp16
        int i = (b - SB - XB) * 256 + tid;
        if (i >= D1 * IN_DIM / 4) return;
        float4 v = ((const float4*)W1)[i];
        ((uint2*)g_W1h)[i] = make_uint2(f2h2(v.x, v.y), f2h2(v.z, v.w));
    } else {                             // W2 fold: 1 block, 256 threads
        __shared__ float cs[256];        // [as2(64) | ad2(64) | fcw(128)]
        if (tid < 64)       cs[tid]       = as2[tid];
        else if (tid < 128) cs[64 + tid - 64]  = ad2[tid - 64];
        else                cs[128 + tid - 128] = fcw[tid - 128];
        __syncthreads();
        int t = tid;                     // channel 0..255
        float d0 = 0.f, d1 = 0.f, d2 = 0.f, d3 = 0.f;
#pragma unroll
        for (int n0 = 0; n0 < D2; n0 += 8) {
            float wv[8];
#pragma unroll
            for (int j = 0; j < 8; j++) wv[j] = W2[(n0 + j) * D1 + t];  // 8-way MLP
#pragma unroll
            for (int j = 0; j < 8; j++) {
                int n = n0 + j;
                d0 += cs[n] * wv[j];
                d1 += cs[64 + n] * wv[j];
                d2 += cs[128 + n] * wv[j];
                d3 += cs[192 + n] * wv[j];
            }
        }
        g_ws4[(t & 7) * 32 + (t >> 3)] = make_float4(d0 * LOG2E, d1 * LOG2E, d2, d3);
    }
}

// ---------------- GEMM1: 64x64 tiles (R11 verbatim), fused alpha1 ----------------
__global__ void __launch_bounds__(256) k_gemm1(
        const float* __restrict__ as1, const float* __restrict__ ad1) {
    extern __shared__ __half smh[];
    __half* As = smh;              // [64][PA]
    __half* Bs = smh + 64 * PA;    // [64][PA]
    int tid = threadIdx.x, lane = tid & 31, warp = tid >> 5;
    int row0 = blockIdx.x * 64, col0 = blockIdx.y * 64;

    for (int idx = tid; idx < 64 * 16; idx += 256) {
        int r = idx >> 4, c = idx & 15;
        *(uint4*)&As[r * PA + c * 8] =
            *(const uint4*)&g_xh[(size_t)(row0 + r) * IN_DIM + c * 8];
    }
    for (int idx = tid; idx < 64 * 16; idx += 256) {
        int r = idx >> 4, c = idx & 15;
        *(uint4*)&Bs[r * PA + c * 8] =
            *(const uint4*)&g_W1h[(size_t)(col0 + r) * IN_DIM + c * 8];
    }
    __syncthreads();

    int wm = warp >> 1, wn = warp & 1;
    int gid = lane >> 2, tig = lane & 3;
    float acc[4][4];
#pragma unroll
    for (int nt = 0; nt < 4; nt++)
#pragma unroll
        for (int j = 0; j < 4; j++) acc[nt][j] = 0.f;

    int ar = lane & 15, ac = (lane >> 4) << 3;
    int bn = ((lane >> 4) << 3) + (lane & 7);
    int bk = ((lane >> 3) & 1) << 3;

#pragma unroll
    for (int ks = 0; ks < 8; ks++) {
        int k0 = ks * 16;
        unsigned a[4];
        unsigned adr = smem_u32(&As[(wm * 16 + ar) * PA + k0 + ac]);
        ldsm_x4(adr, a[0], a[1], a[2], a[3]);
#pragma unroll
        for (int ntp = 0; ntp < 2; ntp++) {
            int n0 = wn * 32 + ntp * 16;
            unsigned b0, b1, b2, b3;
            unsigned bd = smem_u32(&Bs[(n0 + bn) * PA + k0 + bk]);
            ldsm_x4(bd, b0, b1, b2, b3);
            mma16816(acc[ntp * 2],     a, b0, b1);
            mma16816(acc[ntp * 2 + 1], a, b2, b3);
        }
    }

    int rA = row0 + wm * 16 + gid;
    int rB = rA + 8;
#pragma unroll
    for (int nt = 0; nt < 4; nt++) {
        int col = col0 + wn * 32 + nt * 8 + tig * 2;
        *(unsigned*)&g_h1h[(size_t)rA * D1 + col] = f2h2(acc[nt][0], acc[nt][1]);
        *(unsigned*)&g_h1h[(size_t)rB * D1 + col] = f2h2(acc[nt][2], acc[nt][3]);
    }
    float psA = 0.f, pdA = 0.f, psB = 0.f, pdB = 0.f;
#pragma unroll
    for (int nt = 0; nt < 4; nt++) {
        int col = col0 + wn * 32 + nt * 8 + tig * 2;
        float s0 = as1[col], s1 = as1[col + 1];
        float d0 = ad1[col], d1 = ad1[col + 1];
        psA += acc[nt][0] * s0 + acc[nt][1] * s1;
        pdA += acc[nt][0] * d0 + acc[nt][1] * d1;
        psB += acc[nt][2] * s0 + acc[nt][3] * s1;
        pdB += acc[nt][2] * d0 + acc[nt][3] * d1;
    }
#pragma unroll
    for (int off = 1; off < 4; off <<= 1) {
        psA += __shfl_xor_sync(0xffffffffu, psA, off);
        pdA += __shfl_xor_sync(0xffffffffu, pdA, off);
        psB += __shfl_xor_sync(0xffffffffu, psB, off);
        pdB += __shfl_xor_sync(0xffffffffu, pdB, off);
    }
    if (tig == 0) {
        int head = blockIdx.y * 2 + wn;
        g_asrc1[rA * HEADS + head] = psA * LOG2E;
        g_adst1[rA * HEADS + head] = pdA * LOG2E;
        g_asrc1[rB * HEADS + head] = psB * LOG2E;
        g_adst1[rB * HEADS + head] = pdB * LOG2E;
    }
}

// ---------------- k_node2: GEMV out1h @ ws4 -> {asrc2, adst2, z0, z1} ------------
__global__ void __launch_bounds__(256) k_node2(int N) {
    int gt = blockIdx.x * blockDim.x + threadIdx.x;
    int w = gt >> 5, lane = gt & 31;
    if (w >= N) return;
    float4 wv[8];
#pragma unroll
    for (int s = 0; s < 8; s++) wv[s] = g_ws4[s * 32 + lane];
    uint4 u = *(const uint4*)&g_out1h[(size_t)w * D1 + lane * 8];
    const unsigned* up = &u.x;
    float a0 = 0.f, a1 = 0.f, a2 = 0.f, a3 = 0.f;
#pragma unroll
    for (int i = 0; i < 4; i++) {
        float2 f = h2f2(up[i]);
        float4 wa = wv[i * 2], wb = wv[i * 2 + 1];
        a0 += f.x * wa.x + f.y * wb.x;
        a1 += f.x * wa.y + f.y * wb.y;
        a2 += f.x * wa.z + f.y * wb.z;
        a3 += f.x * wa.w + f.y * wb.w;
    }
#pragma unroll
    for (int off = 16; off; off >>= 1) {
        a0 += __shfl_xor_sync(0xffffffffu, a0, off);
        a1 += __shfl_xor_sync(0xffffffffu, a1, off);
        a2 += __shfl_xor_sync(0xffffffffu, a2, off);
        a3 += __shfl_xor_sync(0xffffffffu, a3, off);
    }
    if (lane == 0) {
        g_node2[w] = make_float4(a0, a2, a3, 0.f);
        g_adst2[w] = a1;
    }
}

// ---------------- layer-1 aggregation: R7-shape inner loop ----------------
__device__ __forceinline__ void hacc4(__half2* ha, uint4 u, __half2 w2) {
    ha[0] = __hfma2(*(__half2*)&u.x, w2, ha[0]);
    ha[1] = __hfma2(*(__half2*)&u.y, w2, ha[1]);
    ha[2] = __hfma2(*(__half2*)&u.z, w2, ha[2]);
    ha[3] = __hfma2(*(__half2*)&u.w, w2, ha[3]);
}
__device__ __forceinline__ const uint4* h1row(const __half* Hl, int sH) {
    return (const uint4*)((const char*)Hl + ((size_t)sH << 6));
}

__global__ void __launch_bounds__(256, 6) k_agg1(const float* __restrict__ b1, int N) {
    int gt = blockIdx.x * blockDim.x + threadIdx.x;
    int w = gt >> 5, lane = gt & 31;
    if (w >= N) return;
    int h = lane >> 2;
    float adst = g_adst1[w * HEADS + h];
    ull acc[4];
#pragma unroll
    for (int i = 0; i < 4; i++) acc[i] = 0ull;
    const ull one2 = pack2(1.f);
    float den = 0.f;
    int cnt = g_deg[w]; if (cnt > SLOT) cnt = SLOT;
    const int* row = &g_csr_src[w << SLOT_LG];
    const __half* Hl = g_h1h + lane * 8;

    int e = 0;
    for (; e + 7 < cnt; e += 8) {
        __half2 ha[4];
#pragma unroll
        for (int i = 0; i < 4; i++) ha[i] = __half2half2(__float2half_rn(0.f));
#pragma unroll
        for (int q = 0; q < 2; q++) {
            int b = e + q * 4;
            int s0 = row[b], s1 = row[b + 1], s2 = row[b + 2], s3 = row[b + 3];
            float t0 = g_asrc1[s0 + h] + adst;
            float t1 = g_asrc1[s1 + h] + adst;
            float t2 = g_asrc1[s2 + h] + adst;
            float t3 = g_asrc1[s3 + h] + adst;
            uint4 u0 = *h1row(Hl, s0);
            uint4 u1 = *h1row(Hl, s1);
            uint4 u2 = *h1row(Hl, s2);
            uint4 u3 = *h1row(Hl, s3);
            float w0 = att_w2(t0), w1 = att_w2(t1), w2 = att_w2(t2), w3 = att_w2(t3);
            den += (w0 + w1) + (w2 + w3);
            hacc4(ha, u0, dup_h2(w0));
            hacc4(ha, u1, dup_h2(w1));
            hacc4(ha, u2, dup_h2(w2));
            hacc4(ha, u3, dup_h2(w3));
        }
#pragma unroll
        for (int i = 0; i < 4; i++)
            acc[i] = ffma2(f22ull(__half22float2(ha[i])), one2, acc[i]);
    }
    {   // remainder (<=7 edges)
        __half2 ha[4];
#pragma unroll
        for (int i = 0; i < 4; i++) ha[i] = __half2half2(__float2half_rn(0.f));
        for (; e < cnt; e++) {
            int s = row[e];
            float t = g_asrc1[s + h] + adst;
            uint4 u = *h1row(Hl, s);
            float wg = att_w2(t);
            den += wg;
            hacc4(ha, u, dup_h2(wg));
        }
#pragma unroll
        for (int i = 0; i < 4; i++)
            acc[i] = ffma2(f22ull(__half22float2(ha[i])), one2, acc[i]);
    }

    float inv = 1.f / (den + EPS_DEN);
    float4 bb0 = *(const float4*)&b1[lane * 8];
    float4 bb1 = *(const float4*)&b1[lane * 8 + 4];
    float f[8];
    unpack2(acc[0], f[0], f[1]);
    unpack2(acc[1], f[2], f[3]);
    unpack2(acc[2], f[4], f[5]);
    unpack2(acc[3], f[6], f[7]);
    float o[8];
    o[0] = f[0] * inv + bb0.x; o[1] = f[1] * inv + bb0.y;
    o[2] = f[2] * inv + bb0.z; o[3] = f[3] * inv + bb0.w;
    o[4] = f[4] * inv + bb1.x; o[5] = f[5] * inv + bb1.y;
    o[6] = f[6] * inv + bb1.z; o[7] = f[7] * inv + bb1.w;
#pragma unroll
    for (int i = 0; i < 8; i++) o[i] = (o[i] > 0.f) ? o[i] : (__expf(o[i]) - 1.f);
    uint4 pv;
    pv.x = f2h2(o[0], o[1]); pv.y = f2h2(o[2], o[3]);
    pv.z = f2h2(o[4], o[5]); pv.w = f2h2(o[6], o[7]);
    *(uint4*)&g_out1h[(size_t)w * D1 + lane * 8] = pv;
}

// ---------------- layer-2 agg + fc + log-softmax ----------------
__global__ void __launch_bounds__(256, 6) k_agg2(
        const float* __restrict__ b2, const float* __restrict__ fcw,
        const float* __restrict__ fcb, float* __restrict__ out, int N) {
    int gt = blockIdx.x * blockDim.x + threadIdx.x;
    int w = gt >> 5, lane = gt & 31;
    if (w >= N) return;
    float adst = g_adst2[w];
    float den = 0.f, z0 = 0.f, z1 = 0.f;
    int cnt = g_deg[w]; if (cnt > SLOT) cnt = SLOT;
    const int* row = &g_csr_src[w << SLOT_LG];

    for (int e = lane; e < cnt; e += 32) {
        int sH = row[e];
        float4 nd = *(const float4*)((const char*)g_node2 + ((size_t)sH << 1));
        float t = nd.x + adst;
        float wg = ex2(fmaxf(t, NEG_SLOPE * t));
        den += wg;
        z0 += wg * nd.y;
        z1 += wg * nd.z;
    }
    float bl0 = b2[lane * 2], bl1 = b2[lane * 2 + 1];
    float c0 = bl0 * fcw[lane * 2]      + bl1 * fcw[lane * 2 + 1];
    float c1 = bl0 * fcw[64 + lane * 2] + bl1 * fcw[64 + lane * 2 + 1];
#pragma unroll
    for (int off = 16; off; off >>= 1) {
        den += __shfl_xor_sync(0xffffffffu, den, off);
        z0  += __shfl_xor_sync(0xffffffffu, z0,  off);
        z1  += __shfl_xor_sync(0xffffffffu, z1,  off);
        c0  += __shfl_xor_sync(0xffffffffu, c0,  off);
        c1  += __shfl_xor_sync(0xffffffffu, c1,  off);
    }
    if (lane == 0) {
        g_deg[w] = 0;
        float inv = 1.f / (den + EPS_DEN);
        float l0 = z0 * inv + c0 + fcb[0];
        float l1 = z1 * inv + c1 + fcb[1];
        float m = fmaxf(l0, l1);
        float lse = m + logf(expf(l0 - m) + expf(l1 - m));
        out[(size_t)w * 2 + 0] = l0 - lse;
        out[(size_t)w * 2 + 1] = l1 - lse;
    }
}

// ---------------- launch ----------------
extern "C" void kernel_launch(void* const* d_in, const int* in_sizes, int n_in,
                              void* d_out, int out_size) {
    const float* x   = (const float*)d_in[0];
    const int*   ei  = (const int*)  d_in[1];
    const float* W1  = (const float*)d_in[2];
    const float* as1 = (const float*)d_in[3];
    const float* ad1 = (const float*)d_in[4];
    const float* b1  = (const float*)d_in[5];
    const float* W2  = (const float*)d_in[6];
    const float* as2 = (const float*)d_in[7];
    const float* ad2 = (const float*)d_in[8];
    const float* b2  = (const float*)d_in[9];
    const float* fcw = (const float*)d_in[10];
    const float* fcb = (const float*)d_in[11];
    float* out = (float*)d_out;

    int N  = in_sizes[0] / IN_DIM;
    int E  = in_sizes[1] / 2;
    int ET = E + N;
    int NB64 = (N + 63) / 64;

    const int SMEM = (64 + 64) * PA * 2;   // 34,816 B
    cudaFuncSetAttribute(k_gemm1, cudaFuncAttributeMaxDynamicSharedMemorySize, SMEM);

    // 1: merged scatter + fp16 conversions + W2 fold (fold overlaps the big grid)
    int SB = (ET + 255) / 256;
    int XB = (N * IN_DIM / 4 + 255) / 256;
    int WB = (D1 * IN_DIM / 4 + 255) / 256;
    k_prep<<<SB + XB + WB + 1, 256>>>(x, W1, W2, as2, ad2, fcw, ei, E, N, SB, XB, WB);
    // 2: layer-1 projection + alpha1
    k_gemm1<<<dim3(NB64, 4), 256, SMEM>>>(as1, ad1);
    // 3: layer-1 aggregation (profiled slot)
    k_agg1<<<(N + 7) / 8, 256>>>(b1, N);
    // 4: node2 GEMV (replaces gemm2)
    k_node2<<<(N + 7) / 8, 256>>>(N);
    // 5: layer-2 aggregation + fc + log_softmax (+ g_deg reset)
    k_agg2<<<(N + 7) / 8, 256>>>(b2, fcw, fcb, out, N);
}

// round 17
// speedup vs baseline: 1.7248x; 1.1008x over previous
#include <cuda_runtime.h>
#include <cuda_fp16.h>
#include <math.h>

// ---------------- problem constants ----------------
#define NMAX    50048
#define EMAX    800000
#define IN_DIM  128
#define HEADS   8
#define HID     32
#define D1      256
#define D2      64
#define NEG_SLOPE 0.2f
#define EPS_DEN   1e-16f
#define SLOT    128
#define SLOT_LG 7
#define LOG2E   1.4426950408889634f
#define PA      136     // smem pitch in halves

typedef unsigned long long ull;

// ---------------- device scratch (zero-initialized at module load) ----------------
__device__ __half g_xh[NMAX * IN_DIM];
__device__ __half g_W1h[D1 * IN_DIM];
__device__ __half g_h1h[NMAX * D1];
__device__ float  g_asrc1[NMAX * HEADS]; // pre-scaled by log2(e)
__device__ float  g_adst1[NMAX * HEADS];
__device__ float4 g_node2[NMAX];         // {asrc2*log2e, z0, z1, 0}
__device__ float  g_adst2[NMAX];
__device__ int    g_deg[NMAX];           // zeroed by k_agg2 after final use
__device__ int    g_csr_src[NMAX * SLOT];// stores src*8
__device__ float4 g_ws4[8 * 32];         // W2-folded weights, lane-blocked

// ---------------- helpers ----------------
__device__ __forceinline__ unsigned f2h2(float a, float b) {
    __half2 h = __floats2half2_rn(a, b);
    return *reinterpret_cast<unsigned*>(&h);
}
__device__ __forceinline__ float2 h2f2(unsigned v) {
    __half2 h = *reinterpret_cast<__half2*>(&v);
    return __half22float2(h);
}
__device__ __forceinline__ ull ffma2(ull a, ull b, ull c) {
    ull d;
    asm("fma.rn.f32x2 %0, %1, %2, %3;" : "=l"(d) : "l"(a), "l"(b), "l"(c));
    return d;
}
__device__ __forceinline__ ull pack2(float x) {
    ull d;
    asm("mov.b64 %0, {%1, %1};" : "=l"(d) : "f"(x));
    return d;
}
__device__ __forceinline__ ull f22ull(float2 f) {
    ull d;
    asm("mov.b64 %0, {%1, %2};" : "=l"(d) : "f"(f.x), "f"(f.y));
    return d;
}
__device__ __forceinline__ void unpack2(ull v, float& lo, float& hi) {
    asm("mov.b64 {%0, %1}, %2;" : "=f"(lo), "=f"(hi) : "l"(v));
}
__device__ __forceinline__ float ex2(float x) {
    float y;
    asm("ex2.approx.f32 %0, %1;" : "=f"(y) : "f"(x));
    return y;
}
__device__ __forceinline__ unsigned smem_u32(const void* p) {
    return (unsigned)__cvta_generic_to_shared(p);
}
__device__ __forceinline__ void ldsm_x4(unsigned addr, unsigned& r0, unsigned& r1,
                                        unsigned& r2, unsigned& r3) {
    asm volatile("ldmatrix.sync.aligned.m8n8.x4.shared.b16 {%0,%1,%2,%3}, [%4];"
                 : "=r"(r0), "=r"(r1), "=r"(r2), "=r"(r3) : "r"(addr));
}
__device__ __forceinline__ void mma16816(float* c, const unsigned* a,
                                         unsigned b0, unsigned b1) {
    asm volatile(
        "mma.sync.aligned.m16n8k16.row.col.f32.f16.f16.f32 "
        "{%0,%1,%2,%3}, {%4,%5,%6,%7}, {%8,%9}, {%0,%1,%2,%3};"
        : "+f"(c[0]), "+f"(c[1]), "+f"(c[2]), "+f"(c[3])
        : "r"(a[0]), "r"(a[1]), "r"(a[2]), "r"(a[3]), "r"(b0), "r"(b1));
}
__device__ __forceinline__ float att_w2(float t) {
    return ex2(fmaxf(t, NEG_SLOPE * t));
}
__device__ __forceinline__ __half2 dup_h2(float w) {
    return __floats2half2_rn(w, w);
}

// ---------------- merged prep: scatter | x fp16 | W1 fp16 | W2 fold (1 block) ----
__global__ void k_prep(const float* __restrict__ x,
                       const float* __restrict__ W1, const float* __restrict__ W2,
                       const float* __restrict__ as2, const float* __restrict__ ad2,
                       const float* __restrict__ fcw,
                       const int* __restrict__ ei, int E, int N,
                       int SB, int XB, int WB) {
    int b = blockIdx.x;
    int tid = threadIdx.x;
    if (b < SB) {                        // scatter
        int i = b * 256 + tid;
        int ET = E + N;
        if (i >= ET) return;
        int src, dst;
        if (i < E) { src = ei[i]; dst = ei[E + i]; }
        else       { src = i - E; dst = src; }
        int p = atomicAdd(&g_deg[dst], 1);
        if (p < SLOT) g_csr_src[(dst << SLOT_LG) + p] = src * HEADS;
    } else if (b < SB + XB) {            // x -> fp16
        int i = (b - SB) * 256 + tid;
        int n4 = N * IN_DIM / 4;
        if (i >= n4) return;
        float4 v = ((const float4*)x)[i];
        ((uint2*)g_xh)[i] = make_uint2(f2h2(v.x, v.y), f2h2(v.z, v.w));
    } else if (b < SB + XB + WB) {       // W1 -> fp16
        int i = (b - SB - XB) * 256 + tid;
        if (i >= D1 * IN_DIM / 4) return;
        float4 v = ((const float4*)W1)[i];
        ((uint2*)g_W1h)[i] = make_uint2(f2h2(v.x, v.y), f2h2(v.z, v.w));
    } else {                             // W2 fold: 1 block, 256 threads
        __shared__ float cs[256];        // [as2(64) | ad2(64) | fcw(128)]
        if (tid < 64)       cs[tid]            = as2[tid];
        else if (tid < 128) cs[tid]            = ad2[tid - 64];
        else                cs[tid]            = fcw[tid - 128];
        __syncthreads();
        int t = tid;                     // channel 0..255
        float d0 = 0.f, d1 = 0.f, d2 = 0.f, d3 = 0.f;
#pragma unroll
        for (int n0 = 0; n0 < D2; n0 += 8) {
            float wv[8];
#pragma unroll
            for (int j = 0; j < 8; j++) wv[j] = W2[(n0 + j) * D1 + t];
#pragma unroll
            for (int j = 0; j < 8; j++) {
                int n = n0 + j;
                d0 += cs[n] * wv[j];
                d1 += cs[64 + n] * wv[j];
                d2 += cs[128 + n] * wv[j];
                d3 += cs[192 + n] * wv[j];
            }
        }
        g_ws4[(t & 7) * 32 + (t >> 3)] = make_float4(d0 * LOG2E, d1 * LOG2E, d2, d3);
    }
}

// ---------------- GEMM1: 64x64 tiles, fused alpha1 ----------------
__global__ void __launch_bounds__(256) k_gemm1(
        const float* __restrict__ as1, const float* __restrict__ ad1) {
    extern __shared__ __half smh[];
    __half* As = smh;              // [64][PA]
    __half* Bs = smh + 64 * PA;    // [64][PA]
    int tid = threadIdx.x, lane = tid & 31, warp = tid >> 5;
    int row0 = blockIdx.x * 64, col0 = blockIdx.y * 64;

    for (int idx = tid; idx < 64 * 16; idx += 256) {
        int r = idx >> 4, c = idx & 15;
        *(uint4*)&As[r * PA + c * 8] =
            *(const uint4*)&g_xh[(size_t)(row0 + r) * IN_DIM + c * 8];
    }
    for (int idx = tid; idx < 64 * 16; idx += 256) {
        int r = idx >> 4, c = idx & 15;
        *(uint4*)&Bs[r * PA + c * 8] =
            *(const uint4*)&g_W1h[(size_t)(col0 + r) * IN_DIM + c * 8];
    }
    __syncthreads();

    int wm = warp >> 1, wn = warp & 1;
    int gid = lane >> 2, tig = lane & 3;
    float acc[4][4];
#pragma unroll
    for (int nt = 0; nt < 4; nt++)
#pragma unroll
        for (int j = 0; j < 4; j++) acc[nt][j] = 0.f;

    int ar = lane & 15, ac = (lane >> 4) << 3;
    int bn = ((lane >> 4) << 3) + (lane & 7);
    int bk = ((lane >> 3) & 1) << 3;

#pragma unroll
    for (int ks = 0; ks < 8; ks++) {
        int k0 = ks * 16;
        unsigned a[4];
        unsigned adr = smem_u32(&As[(wm * 16 + ar) * PA + k0 + ac]);
        ldsm_x4(adr, a[0], a[1], a[2], a[3]);
#pragma unroll
        for (int ntp = 0; ntp < 2; ntp++) {
            int n0 = wn * 32 + ntp * 16;
            unsigned b0, b1, b2, b3;
            unsigned bd = smem_u32(&Bs[(n0 + bn) * PA + k0 + bk]);
            ldsm_x4(bd, b0, b1, b2, b3);
            mma16816(acc[ntp * 2],     a, b0, b1);
            mma16816(acc[ntp * 2 + 1], a, b2, b3);
        }
    }

    int rA = row0 + wm * 16 + gid;
    int rB = rA + 8;
#pragma unroll
    for (int nt = 0; nt < 4; nt++) {
        int col = col0 + wn * 32 + nt * 8 + tig * 2;
        *(unsigned*)&g_h1h[(size_t)rA * D1 + col] = f2h2(acc[nt][0], acc[nt][1]);
        *(unsigned*)&g_h1h[(size_t)rB * D1 + col] = f2h2(acc[nt][2], acc[nt][3]);
    }
    float psA = 0.f, pdA = 0.f, psB = 0.f, pdB = 0.f;
#pragma unroll
    for (int nt = 0; nt < 4; nt++) {
        int col = col0 + wn * 32 + nt * 8 + tig * 2;
        float s0 = as1[col], s1 = as1[col + 1];
        float d0 = ad1[col], d1 = ad1[col + 1];
        psA += acc[nt][0] * s0 + acc[nt][1] * s1;
        pdA += acc[nt][0] * d0 + acc[nt][1] * d1;
        psB += acc[nt][2] * s0 + acc[nt][3] * s1;
        pdB += acc[nt][2] * d0 + acc[nt][3] * d1;
    }
#pragma unroll
    for (int off = 1; off < 4; off <<= 1) {
        psA += __shfl_xor_sync(0xffffffffu, psA, off);
        pdA += __shfl_xor_sync(0xffffffffu, pdA, off);
        psB += __shfl_xor_sync(0xffffffffu, psB, off);
        pdB += __shfl_xor_sync(0xffffffffu, pdB, off);
    }
    if (tig == 0) {
        int head = blockIdx.y * 2 + wn;
        g_asrc1[rA * HEADS + head] = psA * LOG2E;
        g_adst1[rA * HEADS + head] = pdA * LOG2E;
        g_asrc1[rB * HEADS + head] = psB * LOG2E;
        g_adst1[rB * HEADS + head] = pdB * LOG2E;
    }
}

// ---------------- layer-1 aggregation + fused node2 functionals ----------------
// Epilogue computes {asrc2, adst2, z0, z1} directly from fp32 out1 values,
// eliminating the out1h store and the separate node2 GEMV kernel.
__device__ __forceinline__ void hacc4(__half2* ha, uint4 u, __half2 w2) {
    ha[0] = __hfma2(*(__half2*)&u.x, w2, ha[0]);
    ha[1] = __hfma2(*(__half2*)&u.y, w2, ha[1]);
    ha[2] = __hfma2(*(__half2*)&u.z, w2, ha[2]);
    ha[3] = __hfma2(*(__half2*)&u.w, w2, ha[3]);
}
__device__ __forceinline__ const uint4* h1row(const __half* Hl, int sH) {
    return (const uint4*)((const char*)Hl + ((size_t)sH << 6));
}

__global__ void __launch_bounds__(256, 6) k_agg1(const float* __restrict__ b1, int N) {
    int gt = blockIdx.x * blockDim.x + threadIdx.x;
    int w = gt >> 5, lane = gt & 31;
    if (w >= N) return;
    int h = lane >> 2;
    float adst = g_adst1[w * HEADS + h];
    ull acc[4];
#pragma unroll
    for (int i = 0; i < 4; i++) acc[i] = 0ull;
    const ull one2 = pack2(1.f);
    float den = 0.f;
    int cnt = g_deg[w]; if (cnt > SLOT) cnt = SLOT;
    const int* row = &g_csr_src[w << SLOT_LG];
    const __half* Hl = g_h1h + lane * 8;

    int e = 0;
    for (; e + 7 < cnt; e += 8) {
        __half2 ha[4];
#pragma unroll
        for (int i = 0; i < 4; i++) ha[i] = __half2half2(__float2half_rn(0.f));
#pragma unroll
        for (int q = 0; q < 2; q++) {
            int b = e + q * 4;
            int s0 = row[b], s1 = row[b + 1], s2 = row[b + 2], s3 = row[b + 3];
            float t0 = g_asrc1[s0 + h] + adst;
            float t1 = g_asrc1[s1 + h] + adst;
            float t2 = g_asrc1[s2 + h] + adst;
            float t3 = g_asrc1[s3 + h] + adst;
            uint4 u0 = *h1row(Hl, s0);
            uint4 u1 = *h1row(Hl, s1);
            uint4 u2 = *h1row(Hl, s2);
            uint4 u3 = *h1row(Hl, s3);
            float w0 = att_w2(t0), w1 = att_w2(t1), w2 = att_w2(t2), w3 = att_w2(t3);
            den += (w0 + w1) + (w2 + w3);
            hacc4(ha, u0, dup_h2(w0));
            hacc4(ha, u1, dup_h2(w1));
            hacc4(ha, u2, dup_h2(w2));
            hacc4(ha, u3, dup_h2(w3));
        }
#pragma unroll
        for (int i = 0; i < 4; i++)
            acc[i] = ffma2(f22ull(__half22float2(ha[i])), one2, acc[i]);
    }
    {   // remainder (<=7 edges)
        __half2 ha[4];
#pragma unroll
        for (int i = 0; i < 4; i++) ha[i] = __half2half2(__float2half_rn(0.f));
        for (; e < cnt; e++) {
            int s = row[e];
            float t = g_asrc1[s + h] + adst;
            uint4 u = *h1row(Hl, s);
            float wg = att_w2(t);
            den += wg;
            hacc4(ha, u, dup_h2(wg));
        }
#pragma unroll
        for (int i = 0; i < 4; i++)
            acc[i] = ffma2(f22ull(__half22float2(ha[i])), one2, acc[i]);
    }

    float inv = 1.f / (den + EPS_DEN);
    float4 bb0 = *(const float4*)&b1[lane * 8];
    float4 bb1 = *(const float4*)&b1[lane * 8 + 4];
    float f[8];
    unpack2(acc[0], f[0], f[1]);
    unpack2(acc[1], f[2], f[3]);
    unpack2(acc[2], f[4], f[5]);
    unpack2(acc[3], f[6], f[7]);
    float o[8];
    o[0] = f[0] * inv + bb0.x; o[1] = f[1] * inv + bb0.y;
    o[2] = f[2] * inv + bb0.z; o[3] = f[3] * inv + bb0.w;
    o[4] = f[4] * inv + bb1.x; o[5] = f[5] * inv + bb1.y;
    o[6] = f[6] * inv + bb1.z; o[7] = f[7] * inv + bb1.w;
#pragma unroll
    for (int i = 0; i < 8; i++) o[i] = (o[i] > 0.f) ? o[i] : (__expf(o[i]) - 1.f);

    // fused node2 functionals: lane owns channels [8*lane, 8*lane+8)
    float a0 = 0.f, a1 = 0.f, a2 = 0.f, a3 = 0.f;
#pragma unroll
    for (int s = 0; s < 8; s++) {
        float4 wv = g_ws4[s * 32 + lane];   // 4 KB table, L1-resident
        a0 += o[s] * wv.x;
        a1 += o[s] * wv.y;
        a2 += o[s] * wv.z;
        a3 += o[s] * wv.w;
    }
#pragma unroll
    for (int off = 16; off; off >>= 1) {
        a0 += __shfl_xor_sync(0xffffffffu, a0, off);
        a1 += __shfl_xor_sync(0xffffffffu, a1, off);
        a2 += __shfl_xor_sync(0xffffffffu, a2, off);
        a3 += __shfl_xor_sync(0xffffffffu, a3, off);
    }
    if (lane == 0) {
        g_node2[w] = make_float4(a0, a2, a3, 0.f);
        g_adst2[w] = a1;
    }
}

// ---------------- layer-2 agg + fc + log-softmax ----------------
__global__ void __launch_bounds__(256, 6) k_agg2(
        const float* __restrict__ b2, const float* __restrict__ fcw,
        const float* __restrict__ fcb, float* __restrict__ out, int N) {
    int gt = blockIdx.x * blockDim.x + threadIdx.x;
    int w = gt >> 5, lane = gt & 31;
    if (w >= N) return;
    float adst = g_adst2[w];
    float den = 0.f, z0 = 0.f, z1 = 0.f;
    int cnt = g_deg[w]; if (cnt > SLOT) cnt = SLOT;
    const int* row = &g_csr_src[w << SLOT_LG];

    for (int e = lane; e < cnt; e += 32) {
        int sH = row[e];
        float4 nd = *(const float4*)((const char*)g_node2 + ((size_t)sH << 1));
        float t = nd.x + adst;
        float wg = ex2(fmaxf(t, NEG_SLOPE * t));
        den += wg;
        z0 += wg * nd.y;
        z1 += wg * nd.z;
    }
    float bl0 = b2[lane * 2], bl1 = b2[lane * 2 + 1];
    float c0 = bl0 * fcw[lane * 2]      + bl1 * fcw[lane * 2 + 1];
    float c1 = bl0 * fcw[64 + lane * 2] + bl1 * fcw[64 + lane * 2 + 1];
#pragma unroll
    for (int off = 16; off; off >>= 1) {
        den += __shfl_xor_sync(0xffffffffu, den, off);
        z0  += __shfl_xor_sync(0xffffffffu, z0,  off);
        z1  += __shfl_xor_sync(0xffffffffu, z1,  off);
        c0  += __shfl_xor_sync(0xffffffffu, c0,  off);
        c1  += __shfl_xor_sync(0xffffffffu, c1,  off);
    }
    if (lane == 0) {
        g_deg[w] = 0;
        float inv = 1.f / (den + EPS_DEN);
        float l0 = z0 * inv + c0 + fcb[0];
        float l1 = z1 * inv + c1 + fcb[1];
        float m = fmaxf(l0, l1);
        float lse = m + logf(expf(l0 - m) + expf(l1 - m));
        out[(size_t)w * 2 + 0] = l0 - lse;
        out[(size_t)w * 2 + 1] = l1 - lse;
    }
}

// ---------------- launch ----------------
extern "C" void kernel_launch(void* const* d_in, const int* in_sizes, int n_in,
                              void* d_out, int out_size) {
    const float* x   = (const float*)d_in[0];
    const int*   ei  = (const int*)  d_in[1];
    const float* W1  = (const float*)d_in[2];
    const float* as1 = (const float*)d_in[3];
    const float* ad1 = (const float*)d_in[4];
    const float* b1  = (const float*)d_in[5];
    const float* W2  = (const float*)d_in[6];
    const float* as2 = (const float*)d_in[7];
    const float* ad2 = (const float*)d_in[8];
    const float* b2  = (const float*)d_in[9];
    const float* fcw = (const float*)d_in[10];
    const float* fcb = (const float*)d_in[11];
    float* out = (float*)d_out;

    int N  = in_sizes[0] / IN_DIM;
    int E  = in_sizes[1] / 2;
    int ET = E + N;
    int NB64 = (N + 63) / 64;

    const int SMEM = (64 + 64) * PA * 2;   // 34,816 B
    cudaFuncSetAttribute(k_gemm1, cudaFuncAttributeMaxDynamicSharedMemorySize, SMEM);

    // 1: merged scatter + fp16 conversions + W2 fold
    int SB = (ET + 255) / 256;
    int XB = (N * IN_DIM / 4 + 255) / 256;
    int WB = (D1 * IN_DIM / 4 + 255) / 256;
    k_prep<<<SB + XB + WB + 1, 256>>>(x, W1, W2, as2, ad2, fcw, ei, E, N, SB, XB, WB);
    // 2: layer-1 projection + alpha1
    k_gemm1<<<dim3(NB64, 4), 256, SMEM>>>(as1, ad1);
    // 3: layer-1 aggregation + node2 functionals (fused)
    k_agg1<<<(N + 7) / 8, 256>>>(b1, N);
    // 4: layer-2 aggregation + fc + log_softmax (+ g_deg reset)  (profiled slot)
    k_agg2<<<(N + 7) / 8, 256>>>(b2, fcw, fcb, out, N);
}